// round 3
// baseline (speedup 1.0000x reference)
#include <cuda_runtime.h>
#include <cuda_bf16.h>
#include <math.h>
#include <stdint.h>

#define CE_BATCH 4096
#define CE_VOCAB 50257

// scratch (no allocation allowed): per-row loss + completion counter
__device__ float g_row_loss[CE_BATCH];
__device__ unsigned int g_done = 0;

// ---------------- scalar fast exp (head/tail only) ----------------
__device__ __forceinline__ float fast_exp(float x) {
    const float LOG2E = 1.4426950408889634f;
    const float MAGIC = 12582912.0f;  // 1.5 * 2^23
    float t  = x * LOG2E;
    float nf = __fadd_rn(t, MAGIC);
    int   ni = __float_as_int(nf);
    float f  = __fadd_rn(t, -__fadd_rn(nf, -MAGIC));
    float p  = 0.0096181291f;
    p = fmaf(p, f, 0.0555041087f);
    p = fmaf(p, f, 0.2402265069f);
    p = fmaf(p, f, 0.6931471806f);
    p = fmaf(p, f, 1.0f);
    return __int_as_float(__float_as_int(p) + (ni << 23));
}

// ---------------- packed f32x2 helpers ----------------
__device__ __forceinline__ unsigned long long pack2(float a, float b) {
    unsigned long long r;
    asm("mov.b64 %0, {%1, %2};" : "=l"(r) : "f"(a), "f"(b));
    return r;
}
__device__ __forceinline__ void unpack2(unsigned long long v, float& a, float& b) {
    asm("mov.b64 {%0, %1}, %2;" : "=f"(a), "=f"(b) : "l"(v));
}

struct ExpConsts {
    unsigned long long LOG2E2, MAGIC2, NEGMAGIC2, ONE2, NEGONE2, C4, C3, C2, C1, C0;
};
__device__ __forceinline__ ExpConsts make_consts() {
    ExpConsts c;
    c.LOG2E2    = pack2(1.4426950408889634f, 1.4426950408889634f);
    c.MAGIC2    = pack2(12582912.0f, 12582912.0f);
    c.NEGMAGIC2 = pack2(-12582912.0f, -12582912.0f);
    c.ONE2      = pack2(1.0f, 1.0f);
    c.NEGONE2   = pack2(-1.0f, -1.0f);
    c.C4        = pack2(0.0096181291f, 0.0096181291f);
    c.C3        = pack2(0.0555041087f, 0.0555041087f);
    c.C2        = pack2(0.2402265069f, 0.2402265069f);
    c.C1        = pack2(0.6931471806f, 0.6931471806f);
    c.C0        = pack2(1.0f, 1.0f);
    return c;
}

// exp of a pair, accumulated into packed acc. All heavy math on packed
// fma-pipe ops (2 lanes/instr); exponent injection on the ALU pipe.
__device__ __forceinline__ void exp_pair_acc(float a, float b, const ExpConsts& c,
                                             unsigned long long& acc) {
    unsigned long long xx = pack2(a, b);
    unsigned long long t, nf, nfm, f, p;
    asm("mul.rn.f32x2 %0, %1, %2;"     : "=l"(t)   : "l"(xx),  "l"(c.LOG2E2));
    asm("add.rn.f32x2 %0, %1, %2;"     : "=l"(nf)  : "l"(t),   "l"(c.MAGIC2));
    asm("fma.rn.f32x2 %0, %1, %2, %3;" : "=l"(nfm) : "l"(nf),  "l"(c.ONE2), "l"(c.NEGMAGIC2)); // nf - MAGIC (exact)
    asm("fma.rn.f32x2 %0, %1, %2, %3;" : "=l"(f)   : "l"(nfm), "l"(c.NEGONE2), "l"(t));        // t - (nf - MAGIC)
    p = c.C4;
    asm("fma.rn.f32x2 %0, %1, %2, %3;" : "=l"(p) : "l"(p), "l"(f), "l"(c.C3));
    asm("fma.rn.f32x2 %0, %1, %2, %3;" : "=l"(p) : "l"(p), "l"(f), "l"(c.C2));
    asm("fma.rn.f32x2 %0, %1, %2, %3;" : "=l"(p) : "l"(p), "l"(f), "l"(c.C1));
    asm("fma.rn.f32x2 %0, %1, %2, %3;" : "=l"(p) : "l"(p), "l"(f), "l"(c.C0));
    // exponent injection per half on the ALU pipe (LEA: shift+add)
    float p0, p1, n0, n1;
    unpack2(p, p0, p1);
    unpack2(nf, n0, n1);
    float r0 = __int_as_float(__float_as_int(p0) + (__float_as_int(n0) << 23));
    float r1 = __int_as_float(__float_as_int(p1) + (__float_as_int(n1) << 23));
    unsigned long long r = pack2(r0, r1);
    asm("add.rn.f32x2 %0, %1, %2;" : "=l"(acc) : "l"(acc), "l"(r));
}

__global__ void __launch_bounds__(256, 4)
ce_kernel(const float* __restrict__ pred, const int* __restrict__ y,
          float* __restrict__ out) {
    const int row = blockIdx.x;
    const int tid = threadIdx.x;
    const float* base = pred + (size_t)row * CE_VOCAB;
    const ExpConsts c = make_consts();

    // peel to 16B alignment (row phase cycles mod 16 bytes)
    uintptr_t addr = (uintptr_t)base;
    int head = (int)(((16u - (unsigned)(addr & 15u)) & 15u) >> 2);  // 0..3
    int n4 = (CE_VOCAB - head) >> 2;
    int tail_start = head + (n4 << 2);

    float s_scalar = 0.0f;
    if (tid < head) s_scalar += fast_exp(base[tid]);
    {
        int i = tail_start + tid;
        if (i < CE_VOCAB) s_scalar += fast_exp(base[i]);
    }

    unsigned long long acc0 = pack2(s_scalar, 0.0f);
    unsigned long long acc1 = pack2(0.0f, 0.0f);

    const float4* v = (const float4*)(base + head);
    #pragma unroll 2
    for (int i = tid; i < n4; i += 256) {
        float4 x = __ldcs(&v[i]);          // streaming: read-once data
        exp_pair_acc(x.x, x.y, c, acc0);
        exp_pair_acc(x.z, x.w, c, acc1);
    }

    float a0, a1, b0, b1;
    unpack2(acc0, a0, a1);
    unpack2(acc1, b0, b1);
    float s = (a0 + a1) + (b0 + b1);

    // block reduction
    #pragma unroll
    for (int o = 16; o > 0; o >>= 1)
        s += __shfl_xor_sync(0xFFFFFFFFu, s, o);

    __shared__ float red[8];
    __shared__ bool amLast;
    int wid  = tid >> 5;
    int lane = tid & 31;
    if (lane == 0) red[wid] = s;
    __syncthreads();

    if (tid == 0) {
        float w = red[0] + red[1] + red[2] + red[3]
                + red[4] + red[5] + red[6] + red[7];
        int label = y[row];
        label = min(max(label, 0), CE_VOCAB - 1);
        float target = __ldg(&base[label]);
        g_row_loss[row] = logf(w) - target;
        __threadfence();
        unsigned int t = atomicAdd(&g_done, 1u);
        amLast = (t == (unsigned)(CE_BATCH - 1));
    }
    __syncthreads();

    // last block to finish folds the 4096 row losses into the scalar mean
    if (amLast) {
        __threadfence();
        float fs = 0.0f;
        #pragma unroll
        for (int i = tid; i < CE_BATCH; i += 256)
            fs += g_row_loss[i];

        #pragma unroll
        for (int o = 16; o > 0; o >>= 1)
            fs += __shfl_xor_sync(0xFFFFFFFFu, fs, o);
        if (lane == 0) red[wid] = fs;
        __syncthreads();
        if (tid == 0) {
            float w = red[0] + red[1] + red[2] + red[3]
                    + red[4] + red[5] + red[6] + red[7];
            out[0] = w * (1.0f / (float)CE_BATCH);
            g_done = 0;   // reset for next graph replay
        }
    }
}

extern "C" void kernel_launch(void* const* d_in, const int* in_sizes, int n_in,
                              void* d_out, int out_size) {
    const float* pred = (const float*)d_in[0];
    const int*   y    = (const int*)d_in[1];
    float*       out  = (float*)d_out;
    (void)in_sizes; (void)n_in; (void)out_size;

    ce_kernel<<<CE_BATCH, 256>>>(pred, y, out);
}

// round 7
// speedup vs baseline: 1.0489x; 1.0489x over previous
#include <cuda_runtime.h>
#include <cuda_bf16.h>
#include <math.h>
#include <stdint.h>

#define CE_BATCH 4096
#define CE_VOCAB 50257

// scratch (no allocation allowed): per-row loss + completion counter
__device__ float g_row_loss[CE_BATCH];
__device__ unsigned int g_done = 0;

// ---------------- scalar fast exp (head/tail only; imm coefficients) ----------------
__device__ __forceinline__ float fast_exp(float x) {
    const float LOG2E = 1.4426950408889634f;
    const float MAGIC = 12582912.0f;  // 1.5 * 2^23
    float t  = x * LOG2E;
    float nf = __fadd_rn(t, MAGIC);
    int   ni = __float_as_int(nf);
    float f  = __fadd_rn(t, -__fadd_rn(nf, -MAGIC));
    float p  = 0.0096181291f;
    p = fmaf(p, f, 0.0555041087f);
    p = fmaf(p, f, 0.2402265069f);
    p = fmaf(p, f, 0.6931471806f);
    p = fmaf(p, f, 1.0f);
    return __int_as_float(__float_as_int(p) + (ni << 23));
}

// ---------------- packed f32x2 helpers ----------------
__device__ __forceinline__ unsigned long long pack2(float a, float b) {
    unsigned long long r;
    asm("mov.b64 %0, {%1, %2};" : "=l"(r) : "f"(a), "f"(b));
    return r;
}
__device__ __forceinline__ void unpack2(unsigned long long v, float& a, float& b) {
    asm("mov.b64 {%0, %1}, %2;" : "=f"(a), "=f"(b) : "l"(v));
}

// 7 packed constants (14 regs) — trimmed for occupancy.
struct ExpConsts {
    unsigned long long LOG2E2, MAGIC2, C4, C3, C2, C1, C0;
};
__device__ __forceinline__ ExpConsts make_consts() {
    ExpConsts c;
    c.LOG2E2 = pack2(1.4426950408889634f, 1.4426950408889634f);
    c.MAGIC2 = pack2(12582912.0f, 12582912.0f);
    c.C4     = pack2(0.0096181291f, 0.0096181291f);
    c.C3     = pack2(0.0555041087f, 0.0555041087f);
    c.C2     = pack2(0.2402265069f, 0.2402265069f);
    c.C1     = pack2(0.6931471806f, 0.6931471806f);
    c.C0     = pack2(1.0f, 1.0f);
    return c;
}

// exp of a packed pair (already-packed 64-bit input), accumulated into packed acc.
// 9 packed fma-pipe ops per 2 elements; exponent injection on the ALU pipe.
__device__ __forceinline__ void exp_pair_acc(unsigned long long xx, const ExpConsts& c,
                                             unsigned long long& acc) {
    unsigned long long t, nf, d, f, p;
    asm("mul.rn.f32x2 %0, %1, %2;"     : "=l"(t)  : "l"(xx), "l"(c.LOG2E2));
    asm("add.rn.f32x2 %0, %1, %2;"     : "=l"(nf) : "l"(t),  "l"(c.MAGIC2));
    asm("sub.rn.f32x2 %0, %1, %2;"     : "=l"(d)  : "l"(nf), "l"(c.MAGIC2));  // n (exact)
    asm("sub.rn.f32x2 %0, %1, %2;"     : "=l"(f)  : "l"(t),  "l"(d));         // f = t - n
    p = c.C4;
    asm("fma.rn.f32x2 %0, %1, %2, %3;" : "=l"(p) : "l"(p), "l"(f), "l"(c.C3));
    asm("fma.rn.f32x2 %0, %1, %2, %3;" : "=l"(p) : "l"(p), "l"(f), "l"(c.C2));
    asm("fma.rn.f32x2 %0, %1, %2, %3;" : "=l"(p) : "l"(p), "l"(f), "l"(c.C1));
    asm("fma.rn.f32x2 %0, %1, %2, %3;" : "=l"(p) : "l"(p), "l"(f), "l"(c.C0));
    // exponent injection per half (LEA shift+add on ALU pipe)
    float p0, p1, n0, n1;
    unpack2(p, p0, p1);
    unpack2(nf, n0, n1);
    float r0 = __int_as_float(__float_as_int(p0) + (__float_as_int(n0) << 23));
    float r1 = __int_as_float(__float_as_int(p1) + (__float_as_int(n1) << 23));
    unsigned long long r = pack2(r0, r1);
    asm("add.rn.f32x2 %0, %1, %2;" : "=l"(acc) : "l"(acc), "l"(r));
}

__global__ void __launch_bounds__(256, 7)
ce_kernel(const float* __restrict__ pred, const int* __restrict__ y,
          float* __restrict__ out) {
    const int row = blockIdx.x;
    const int tid = threadIdx.x;
    const float* base = pred + (size_t)row * CE_VOCAB;
    const ExpConsts c = make_consts();

    // peel to 16B alignment (row phase cycles mod 16 bytes)
    uintptr_t addr = (uintptr_t)base;
    int head = (int)(((16u - (unsigned)(addr & 15u)) & 15u) >> 2);  // 0..3
    int n4 = (CE_VOCAB - head) >> 2;
    int tail_start = head + (n4 << 2);

    float s_scalar = 0.0f;
    if (tid < head) s_scalar += fast_exp(base[tid]);
    {
        int i = tail_start + tid;
        if (i < CE_VOCAB) s_scalar += fast_exp(base[i]);
    }

    unsigned long long acc0 = pack2(s_scalar, 0.0f);
    unsigned long long acc1 = pack2(0.0f, 0.0f);

    // 16B-aligned vector view; each ulonglong2 = 4 floats, pairs born packed.
    const ulonglong2* v = (const ulonglong2*)(base + head);
    int i = tid;
    int limit = n4 - 256;   // room for i and i+256
    // main loop: 2 front-batched LDG.128 per iteration (MLP_p1 = 2)
    for (; i < limit; i += 512) {
        ulonglong2 a = v[i];
        ulonglong2 b = v[i + 256];
        exp_pair_acc(a.x, c, acc0);
        exp_pair_acc(a.y, c, acc1);
        exp_pair_acc(b.x, c, acc0);
        exp_pair_acc(b.y, c, acc1);
    }
    if (i < n4) {
        ulonglong2 a = v[i];
        exp_pair_acc(a.x, c, acc0);
        exp_pair_acc(a.y, c, acc1);
    }

    float a0, a1, b0, b1;
    unpack2(acc0, a0, a1);
    unpack2(acc1, b0, b1);
    float s = (a0 + a1) + (b0 + b1);

    // block reduction
    #pragma unroll
    for (int o = 16; o > 0; o >>= 1)
        s += __shfl_xor_sync(0xFFFFFFFFu, s, o);

    __shared__ float red[8];
    __shared__ bool amLast;
    int wid  = tid >> 5;
    int lane = tid & 31;
    if (lane == 0) red[wid] = s;
    __syncthreads();

    if (tid == 0) {
        float w = red[0] + red[1] + red[2] + red[3]
                + red[4] + red[5] + red[6] + red[7];
        int label = y[row];
        label = min(max(label, 0), CE_VOCAB - 1);
        float target = __ldg(&base[label]);
        g_row_loss[row] = logf(w) - target;
        __threadfence();
        unsigned int t = atomicAdd(&g_done, 1u);
        amLast = (t == (unsigned)(CE_BATCH - 1));
    }
    __syncthreads();

    // last block folds the 4096 row losses into the scalar mean
    if (amLast) {
        __threadfence();
        float fs = 0.0f;
        #pragma unroll
        for (int i2 = tid; i2 < CE_BATCH; i2 += 256)
            fs += g_row_loss[i2];

        #pragma unroll
        for (int o = 16; o > 0; o >>= 1)
            fs += __shfl_xor_sync(0xFFFFFFFFu, fs, o);
        if (lane == 0) red[wid] = fs;
        __syncthreads();
        if (tid == 0) {
            float w = red[0] + red[1] + red[2] + red[3]
                    + red[4] + red[5] + red[6] + red[7];
            out[0] = w * (1.0f / (float)CE_BATCH);
            g_done = 0;   // reset for next graph replay
        }
    }
}

extern "C" void kernel_launch(void* const* d_in, const int* in_sizes, int n_in,
                              void* d_out, int out_size) {
    const float* pred = (const float*)d_in[0];
    const int*   y    = (const int*)d_in[1];
    float*       out  = (float*)d_out;
    (void)in_sizes; (void)n_in; (void)out_size;

    ce_kernel<<<CE_BATCH, 256>>>(pred, y, out);
}

// round 9
// speedup vs baseline: 1.0851x; 1.0345x over previous
#include <cuda_runtime.h>
#include <cuda_bf16.h>
#include <math.h>
#include <stdint.h>

#define CE_BATCH 4096
#define CE_VOCAB 50257

// scratch (no allocation allowed): per-row loss + completion counter
__device__ float g_row_loss[CE_BATCH];
__device__ unsigned int g_done = 0;

// ---------------- scalar fast exp (head/tail only; imm coefficients) ----------------
__device__ __forceinline__ float fast_exp(float x) {
    const float LOG2E = 1.4426950408889634f;
    const float MAGIC = 12582912.0f;  // 1.5 * 2^23
    float t  = x * LOG2E;
    float nf = __fadd_rn(t, MAGIC);
    int   ni = __float_as_int(nf);
    float f  = __fadd_rn(t, -__fadd_rn(nf, -MAGIC));
    float p  = 0.0096181291f;
    p = fmaf(p, f, 0.0555041087f);
    p = fmaf(p, f, 0.2402265069f);
    p = fmaf(p, f, 0.6931471806f);
    p = fmaf(p, f, 1.0f);
    return __int_as_float(__float_as_int(p) + (ni << 23));
}

// ---------------- packed f32x2 helpers ----------------
__device__ __forceinline__ unsigned long long pack2(float a, float b) {
    unsigned long long r;
    asm("mov.b64 %0, {%1, %2};" : "=l"(r) : "f"(a), "f"(b));
    return r;
}
__device__ __forceinline__ void unpack2(unsigned long long v, float& a, float& b) {
    asm("mov.b64 {%0, %1}, %2;" : "=f"(a), "=f"(b) : "l"(v));
}

// 7 packed constants (14 regs)
struct ExpConsts {
    unsigned long long LOG2E2, MAGIC2, C4, C3, C2, C1, C0;
};
__device__ __forceinline__ ExpConsts make_consts() {
    ExpConsts c;
    c.LOG2E2 = pack2(1.4426950408889634f, 1.4426950408889634f);
    c.MAGIC2 = pack2(12582912.0f, 12582912.0f);
    c.C4     = pack2(0.0096181291f, 0.0096181291f);
    c.C3     = pack2(0.0555041087f, 0.0555041087f);
    c.C2     = pack2(0.2402265069f, 0.2402265069f);
    c.C1     = pack2(0.6931471806f, 0.6931471806f);
    c.C0     = pack2(1.0f, 1.0f);
    return c;
}

// exp of a packed pair, accumulated into packed acc. 9 packed fma-pipe ops
// per 2 elements; exponent injection on the ALU pipe.
__device__ __forceinline__ void exp_pair_acc(unsigned long long xx, const ExpConsts& c,
                                             unsigned long long& acc) {
    unsigned long long t, nf, d, f, p;
    asm("mul.rn.f32x2 %0, %1, %2;"     : "=l"(t)  : "l"(xx), "l"(c.LOG2E2));
    asm("add.rn.f32x2 %0, %1, %2;"     : "=l"(nf) : "l"(t),  "l"(c.MAGIC2));
    asm("sub.rn.f32x2 %0, %1, %2;"     : "=l"(d)  : "l"(nf), "l"(c.MAGIC2));  // n (exact)
    asm("sub.rn.f32x2 %0, %1, %2;"     : "=l"(f)  : "l"(t),  "l"(d));         // f = t - n
    p = c.C4;
    asm("fma.rn.f32x2 %0, %1, %2, %3;" : "=l"(p) : "l"(p), "l"(f), "l"(c.C3));
    asm("fma.rn.f32x2 %0, %1, %2, %3;" : "=l"(p) : "l"(p), "l"(f), "l"(c.C2));
    asm("fma.rn.f32x2 %0, %1, %2, %3;" : "=l"(p) : "l"(p), "l"(f), "l"(c.C1));
    asm("fma.rn.f32x2 %0, %1, %2, %3;" : "=l"(p) : "l"(p), "l"(f), "l"(c.C0));
    float p0, p1, n0, n1;
    unpack2(p, p0, p1);
    unpack2(nf, n0, n1);
    float r0 = __int_as_float(__float_as_int(p0) + (__float_as_int(n0) << 23));
    float r1 = __int_as_float(__float_as_int(p1) + (__float_as_int(n1) << 23));
    unsigned long long r = pack2(r0, r1);
    asm("add.rn.f32x2 %0, %1, %2;" : "=l"(acc) : "l"(acc), "l"(r));
}

__global__ void __launch_bounds__(256, 6)
ce_kernel(const float* __restrict__ pred, const int* __restrict__ y,
          float* __restrict__ out) {
    const int row = blockIdx.x;
    const int tid = threadIdx.x;
    const float* base = pred + (size_t)row * CE_VOCAB;
    const ExpConsts c = make_consts();

    // peel to 16B alignment (row phase cycles mod 16 bytes)
    uintptr_t addr = (uintptr_t)base;
    int head = (int)(((16u - (unsigned)(addr & 15u)) & 15u) >> 2);  // 0..3
    int n4 = (CE_VOCAB - head) >> 2;
    int tail_start = head + (n4 << 2);

    float s_scalar = 0.0f;
    if (tid < head) s_scalar += fast_exp(base[tid]);
    {
        int i = tail_start + tid;
        if (i < CE_VOCAB) s_scalar += fast_exp(base[i]);
    }

    unsigned long long acc0 = pack2(s_scalar, 0.0f);
    unsigned long long acc1 = pack2(0.0f, 0.0f);

    // 16B-aligned vector view; each ulonglong2 = 4 floats, pairs born packed.
    const ulonglong2* v = (const ulonglong2*)(base + head);
    int i = tid;
    int limit = n4 - 768;   // room for i .. i+768
    // main loop: 4 front-batched LDG.128 per iteration (~24.6 KB in flight/SM)
    for (; i < limit; i += 1024) {
        ulonglong2 a = v[i];
        ulonglong2 b = v[i + 256];
        ulonglong2 d = v[i + 512];
        ulonglong2 e = v[i + 768];
        exp_pair_acc(a.x, c, acc0);
        exp_pair_acc(a.y, c, acc1);
        exp_pair_acc(b.x, c, acc0);
        exp_pair_acc(b.y, c, acc1);
        exp_pair_acc(d.x, c, acc0);
        exp_pair_acc(d.y, c, acc1);
        exp_pair_acc(e.x, c, acc0);
        exp_pair_acc(e.y, c, acc1);
    }
    // remainder: up to 3 single-load passes
    for (; i < n4; i += 256) {
        ulonglong2 a = v[i];
        exp_pair_acc(a.x, c, acc0);
        exp_pair_acc(a.y, c, acc1);
    }

    float a0, a1, b0, b1;
    unpack2(acc0, a0, a1);
    unpack2(acc1, b0, b1);
    float s = (a0 + a1) + (b0 + b1);

    // block reduction
    #pragma unroll
    for (int o = 16; o > 0; o >>= 1)
        s += __shfl_xor_sync(0xFFFFFFFFu, s, o);

    __shared__ float red[8];
    __shared__ bool amLast;
    int wid  = tid >> 5;
    int lane = tid & 31;
    if (lane == 0) red[wid] = s;
    __syncthreads();

    if (tid == 0) {
        float w = red[0] + red[1] + red[2] + red[3]
                + red[4] + red[5] + red[6] + red[7];
        int label = y[row];
        label = min(max(label, 0), CE_VOCAB - 1);
        float target = __ldg(&base[label]);
        g_row_loss[row] = logf(w) - target;
        __threadfence();
        unsigned int t = atomicAdd(&g_done, 1u);
        amLast = (t == (unsigned)(CE_BATCH - 1));
    }
    __syncthreads();

    // last block folds the 4096 row losses into the scalar mean
    if (amLast) {
        __threadfence();
        float fs = 0.0f;
        #pragma unroll
        for (int i2 = tid; i2 < CE_BATCH; i2 += 256)
            fs += g_row_loss[i2];

        #pragma unroll
        for (int o = 16; o > 0; o >>= 1)
            fs += __shfl_xor_sync(0xFFFFFFFFu, fs, o);
        if (lane == 0) red[wid] = fs;
        __syncthreads();
        if (tid == 0) {
            float w = red[0] + red[1] + red[2] + red[3]
                    + red[4] + red[5] + red[6] + red[7];
            out[0] = w * (1.0f / (float)CE_BATCH);
            g_done = 0;   // reset for next graph replay
        }
    }
}

extern "C" void kernel_launch(void* const* d_in, const int* in_sizes, int n_in,
                              void* d_out, int out_size) {
    const float* pred = (const float*)d_in[0];
    const int*   y    = (const int*)d_in[1];
    float*       out  = (float*)d_out;
    (void)in_sizes; (void)n_in; (void)out_size;

    ce_kernel<<<CE_BATCH, 256>>>(pred, y, out);
}

// round 10
// speedup vs baseline: 1.1159x; 1.0285x over previous
#include <cuda_runtime.h>
#include <cuda_bf16.h>
#include <math.h>
#include <stdint.h>

#define CE_BATCH 4096
#define CE_VOCAB 50257
#define CHUNK_U2 1024          // 1024 x 16B = 16 KB per chunk
#define NSTAGE   2

// scratch (no allocation allowed): per-row loss + completion counter
__device__ float g_row_loss[CE_BATCH];
__device__ unsigned int g_done = 0;

// ---------------- scalar fast exp (head/tail only) ----------------
__device__ __forceinline__ float fast_exp(float x) {
    const float LOG2E = 1.4426950408889634f;
    const float MAGIC = 12582912.0f;
    float t  = x * LOG2E;
    float nf = __fadd_rn(t, MAGIC);
    int   ni = __float_as_int(nf);
    float f  = __fadd_rn(t, -__fadd_rn(nf, -MAGIC));
    float p  = 0.0096181291f;
    p = fmaf(p, f, 0.0555041087f);
    p = fmaf(p, f, 0.2402265069f);
    p = fmaf(p, f, 0.6931471806f);
    p = fmaf(p, f, 1.0f);
    return __int_as_float(__float_as_int(p) + (ni << 23));
}

// ---------------- packed f32x2 helpers ----------------
__device__ __forceinline__ unsigned long long pack2(float a, float b) {
    unsigned long long r;
    asm("mov.b64 %0, {%1, %2};" : "=l"(r) : "f"(a), "f"(b));
    return r;
}
__device__ __forceinline__ void unpack2(unsigned long long v, float& a, float& b) {
    asm("mov.b64 {%0, %1}, %2;" : "=f"(a), "=f"(b) : "l"(v));
}

struct ExpConsts {
    unsigned long long LOG2E2, MAGIC2, C4, C3, C2, C1, C0;
};
__device__ __forceinline__ ExpConsts make_consts() {
    ExpConsts c;
    c.LOG2E2 = pack2(1.4426950408889634f, 1.4426950408889634f);
    c.MAGIC2 = pack2(12582912.0f, 12582912.0f);
    c.C4     = pack2(0.0096181291f, 0.0096181291f);
    c.C3     = pack2(0.0555041087f, 0.0555041087f);
    c.C2     = pack2(0.2402265069f, 0.2402265069f);
    c.C1     = pack2(0.6931471806f, 0.6931471806f);
    c.C0     = pack2(1.0f, 1.0f);
    return c;
}

// exp of a packed pair, accumulated into packed acc (9 packed fma-pipe ops / 2 elems)
__device__ __forceinline__ void exp_pair_acc(unsigned long long xx, const ExpConsts& c,
                                             unsigned long long& acc) {
    unsigned long long t, nf, d, f, p;
    asm("mul.rn.f32x2 %0, %1, %2;"     : "=l"(t)  : "l"(xx), "l"(c.LOG2E2));
    asm("add.rn.f32x2 %0, %1, %2;"     : "=l"(nf) : "l"(t),  "l"(c.MAGIC2));
    asm("sub.rn.f32x2 %0, %1, %2;"     : "=l"(d)  : "l"(nf), "l"(c.MAGIC2));
    asm("sub.rn.f32x2 %0, %1, %2;"     : "=l"(f)  : "l"(t),  "l"(d));
    p = c.C4;
    asm("fma.rn.f32x2 %0, %1, %2, %3;" : "=l"(p) : "l"(p), "l"(f), "l"(c.C3));
    asm("fma.rn.f32x2 %0, %1, %2, %3;" : "=l"(p) : "l"(p), "l"(f), "l"(c.C2));
    asm("fma.rn.f32x2 %0, %1, %2, %3;" : "=l"(p) : "l"(p), "l"(f), "l"(c.C1));
    asm("fma.rn.f32x2 %0, %1, %2, %3;" : "=l"(p) : "l"(p), "l"(f), "l"(c.C0));
    float p0, p1, n0, n1;
    unpack2(p, p0, p1);
    unpack2(nf, n0, n1);
    float r0 = __int_as_float(__float_as_int(p0) + (__float_as_int(n0) << 23));
    float r1 = __int_as_float(__float_as_int(p1) + (__float_as_int(n1) << 23));
    unsigned long long r = pack2(r0, r1);
    asm("add.rn.f32x2 %0, %1, %2;" : "=l"(acc) : "l"(acc), "l"(r));
}

// ---------------- mbarrier / bulk-copy wrappers ----------------
__device__ __forceinline__ uint32_t smem_u32(const void* p) {
    return (uint32_t)__cvta_generic_to_shared(p);
}
__device__ __forceinline__ void mbar_init(uint32_t mbar, uint32_t count) {
    asm volatile("mbarrier.init.shared.b64 [%0], %1;" :: "r"(mbar), "r"(count) : "memory");
}
__device__ __forceinline__ void mbar_expect_tx(uint32_t mbar, uint32_t bytes) {
    asm volatile("mbarrier.arrive.expect_tx.shared.b64 _, [%0], %1;"
                 :: "r"(mbar), "r"(bytes) : "memory");
}
__device__ __forceinline__ void bulk_g2s(uint32_t dst, const void* src, uint32_t bytes,
                                         uint32_t mbar) {
    asm volatile("cp.async.bulk.shared::cluster.global.mbarrier::complete_tx::bytes "
                 "[%0], [%1], %2, [%3];"
                 :: "r"(dst), "l"(src), "r"(bytes), "r"(mbar) : "memory");
}
__device__ __forceinline__ void mbar_wait(uint32_t mbar, uint32_t parity) {
    uint32_t done;
    asm volatile(
        "{\n\t.reg .pred p;\n\t"
        "mbarrier.try_wait.parity.acquire.cta.shared::cta.b64 p, [%1], %2;\n\t"
        "selp.b32 %0, 1, 0, p;\n\t}"
        : "=r"(done) : "r"(mbar), "r"(parity) : "memory");
    if (!done) {
        asm volatile(
            "{\n\t.reg .pred P1;\n\t"
            "WL_%=:\n\t"
            "mbarrier.try_wait.parity.acquire.cta.shared::cta.b64 P1, [%0], %1, 0x989680;\n\t"
            "@P1 bra.uni WD_%=;\n\t"
            "bra.uni WL_%=;\n\t"
            "WD_%=:\n\t}"
            :: "r"(mbar), "r"(parity) : "memory");
    }
}

__global__ void __launch_bounds__(256, 6)
ce_kernel(const float* __restrict__ pred, const int* __restrict__ y,
          float* __restrict__ out) {
    __shared__ __align__(16) ulonglong2 buf[NSTAGE][CHUNK_U2];   // 32 KB
    __shared__ __align__(8)  unsigned long long mbar_storage[NSTAGE];
    __shared__ float red[8];
    __shared__ bool amLast;

    const int row = blockIdx.x;
    const int tid = threadIdx.x;
    const float* base = pred + (size_t)row * CE_VOCAB;
    const ExpConsts c = make_consts();

    // peel to 16B alignment (row phase cycles mod 16 bytes)
    uintptr_t addr = (uintptr_t)base;
    int head = (int)(((16u - (unsigned)(addr & 15u)) & 15u) >> 2);  // 0..3
    int n4 = (CE_VOCAB - head) >> 2;                                 // 16B units
    int tail_start = head + (n4 << 2);

    float s_scalar = 0.0f;
    if (tid < head) s_scalar += fast_exp(base[tid]);
    {
        int i = tail_start + tid;
        if (i < CE_VOCAB) s_scalar += fast_exp(base[i]);
    }

    const char* src = (const char*)(base + head);
    const int NC = (n4 + CHUNK_U2 - 1) >> 10;   // number of 16KB chunks

    uint32_t mb0 = smem_u32(&mbar_storage[0]);
    uint32_t mb1 = smem_u32(&mbar_storage[1]);

    if (tid == 0) {
        mbar_init(mb0, 1);
        mbar_init(mb1, 1);
    }
    __syncthreads();

    // prefetch the first NSTAGE chunks
    if (tid == 0) {
        #pragma unroll
        for (int s = 0; s < NSTAGE; s++) {
            if (s < NC) {
                int cbase = s << 10;
                uint32_t bytes = (uint32_t)(min(CHUNK_U2, n4 - cbase)) * 16u;
                uint32_t mb = s ? mb1 : mb0;
                mbar_expect_tx(mb, bytes);
                bulk_g2s(smem_u32(&buf[s][0]), src + ((size_t)cbase << 4), bytes, mb);
            }
        }
    }

    unsigned long long acc0 = pack2(s_scalar, 0.0f);
    unsigned long long acc1 = pack2(0.0f, 0.0f);

    for (int ck = 0; ck < NC; ck++) {
        int stage = ck & 1;
        uint32_t mb = stage ? mb1 : mb0;
        uint32_t parity = (ck >> 1) & 1;
        mbar_wait(mb, parity);

        int cbase = ck << 10;
        int cnt = min(CHUNK_U2, n4 - cbase);
        if (cnt == CHUNK_U2) {
            #pragma unroll
            for (int k = 0; k < CHUNK_U2 / 256; k++) {
                ulonglong2 xv = buf[stage][tid + (k << 8)];
                exp_pair_acc(xv.x, c, acc0);
                exp_pair_acc(xv.y, c, acc1);
            }
        } else {
            for (int j = tid; j < cnt; j += 256) {
                ulonglong2 xv = buf[stage][j];
                exp_pair_acc(xv.x, c, acc0);
                exp_pair_acc(xv.y, c, acc1);
            }
        }
        __syncthreads();   // everyone done reading buf[stage]

        int nxt = ck + NSTAGE;
        if (tid == 0 && nxt < NC) {
            int nbase = nxt << 10;
            uint32_t bytes = (uint32_t)(min(CHUNK_U2, n4 - nbase)) * 16u;
            mbar_expect_tx(mb, bytes);
            bulk_g2s(smem_u32(&buf[stage][0]), src + ((size_t)nbase << 4), bytes, mb);
        }
    }

    float a0, a1, b0, b1;
    unpack2(acc0, a0, a1);
    unpack2(acc1, b0, b1);
    float s = (a0 + a1) + (b0 + b1);

    // block reduction
    #pragma unroll
    for (int o = 16; o > 0; o >>= 1)
        s += __shfl_xor_sync(0xFFFFFFFFu, s, o);

    int wid  = tid >> 5;
    int lane = tid & 31;
    if (lane == 0) red[wid] = s;
    __syncthreads();

    if (tid == 0) {
        float w = red[0] + red[1] + red[2] + red[3]
                + red[4] + red[5] + red[6] + red[7];
        int label = y[row];
        label = min(max(label, 0), CE_VOCAB - 1);
        float target = __ldg(&base[label]);
        g_row_loss[row] = logf(w) - target;
        __threadfence();
        unsigned int t = atomicAdd(&g_done, 1u);
        amLast = (t == (unsigned)(CE_BATCH - 1));
    }
    __syncthreads();

    // last block folds the 4096 row losses into the scalar mean
    if (amLast) {
        __threadfence();
        float fs = 0.0f;
        #pragma unroll
        for (int i2 = tid; i2 < CE_BATCH; i2 += 256)
            fs += g_row_loss[i2];

        #pragma unroll
        for (int o = 16; o > 0; o >>= 1)
            fs += __shfl_xor_sync(0xFFFFFFFFu, fs, o);
        if (lane == 0) red[wid] = fs;
        __syncthreads();
        if (tid == 0) {
            float w = red[0] + red[1] + red[2] + red[3]
                    + red[4] + red[5] + red[6] + red[7];
            out[0] = w * (1.0f / (float)CE_BATCH);
            g_done = 0;   // reset for next graph replay
        }
    }
}

extern "C" void kernel_launch(void* const* d_in, const int* in_sizes, int n_in,
                              void* d_out, int out_size) {
    const float* pred = (const float*)d_in[0];
    const int*   y    = (const int*)d_in[1];
    float*       out  = (float*)d_out;
    (void)in_sizes; (void)n_in; (void)out_size;

    ce_kernel<<<CE_BATCH, 256>>>(pred, y, out);
}